// round 1
// baseline (speedup 1.0000x reference)
#include <cuda_runtime.h>
#include <math.h>

// ---------------- problem constants ----------------
#define BATCH 64
#define Hdim  56
#define Wdim  56
#define Cdim  128
#define HEADS 4
#define WSz   7
#define WS2   49
#define HID   512
#define PT    4           // top/left pad = WS - SHIFT = 4
#define PL    4
#define NWG   9           // windows per side (63/7)
#define NTOK  (BATCH*Hdim*Wdim)     // 200704
#define NWIN  (BATCH*NWG*NWG)       // 5184

// ---------------- scratch (no cudaMalloc allowed) ----------------
__device__ float g_xn[(size_t)NTOK * Cdim];   // LN output (reused for LN2)
__device__ float g_x2[(size_t)NTOK * Cdim];   // after spatial residual
__device__ float g_h [(size_t)NTOK * HID];    // MLP hidden

// ---------------- LayerNorm: one warp per token (C=128 = 32 lanes x float4) ----
__global__ void ln_kernel(const float* __restrict__ x,
                          const float* __restrict__ g,
                          const float* __restrict__ b,
                          float* __restrict__ out)
{
    int warp = (blockIdx.x * blockDim.x + threadIdx.x) >> 5;
    int lane = threadIdx.x & 31;
    if (warp >= NTOK) return;

    const float4 v = *(const float4*)(x + (size_t)warp * Cdim + lane * 4);
    float s  = v.x + v.y + v.z + v.w;
    float s2 = v.x*v.x + v.y*v.y + v.z*v.z + v.w*v.w;
    #pragma unroll
    for (int o = 16; o; o >>= 1) {
        s  += __shfl_xor_sync(0xffffffffu, s,  o);
        s2 += __shfl_xor_sync(0xffffffffu, s2, o);
    }
    float mu  = s * (1.0f / Cdim);
    float var = s2 * (1.0f / Cdim) - mu * mu;
    float inv = rsqrtf(var + 1e-5f);

    float4 gg = *(const float4*)(g + lane * 4);
    float4 bb = *(const float4*)(b + lane * 4);
    float4 o4;
    o4.x = (v.x - mu) * inv * gg.x + bb.x;
    o4.y = (v.y - mu) * inv * gg.y + bb.y;
    o4.z = (v.z - mu) * inv * gg.z + bb.z;
    o4.w = (v.w - mu) * inv * gg.w + bb.w;
    *(float4*)(out + (size_t)warp * Cdim + lane * 4) = o4;
}

// ---------------- shifted-window token mixing + residual ----------------
// One block per window. Loads the 49x128 window tile (zero-padded at image
// border) and the full (4,49,49) spatial weights into smem, then each thread
// computes output positions (i, c): y = sum_j w[h][i][j] * x[j][c] + b[h][i].
// Writes x2 = x + y only for positions inside the crop (all 56x56 tokens are
// covered exactly once since windows are disjoint).
#define SPATIAL_SMEM ((WS2*Cdim + HEADS*WS2*WS2) * sizeof(float))  // 63504 B

__global__ void spatial_kernel(const float* __restrict__ xn,
                               const float* __restrict__ x,
                               const float* __restrict__ sw,
                               const float* __restrict__ sb,
                               float* __restrict__ x2)
{
    extern __shared__ float smem[];
    float* s_x = smem;                 // [49][128]
    float* s_w = smem + WS2 * Cdim;    // [4*49*49]

    int win = blockIdx.x;
    int b   = win / (NWG * NWG);
    int wi  = win % (NWG * NWG);
    int wh  = wi / NWG;
    int ww  = wi % NWG;

    // load window tile (with shift padding -> zeros outside image)
    for (int idx = threadIdx.x; idx < WS2 * Cdim; idx += blockDim.x) {
        int j = idx >> 7, c = idx & 127;
        int hs = wh * WSz + j / WSz - PT;
        int ws = ww * WSz + j % WSz - PL;
        float v = 0.0f;
        if ((unsigned)hs < (unsigned)Hdim && (unsigned)ws < (unsigned)Wdim)
            v = xn[((size_t)b * (Hdim*Wdim) + hs * Wdim + ws) * Cdim + c];
        s_x[idx] = v;
    }
    // load spatial weights
    for (int idx = threadIdx.x; idx < HEADS * WS2 * WS2; idx += blockDim.x)
        s_w[idx] = sw[idx];
    __syncthreads();

    for (int idx = threadIdx.x; idx < WS2 * Cdim; idx += blockDim.x) {
        int i = idx >> 7, c = idx & 127;
        int hs = wh * WSz + i / WSz - PT;
        int ws = ww * WSz + i % WSz - PL;
        if ((unsigned)hs >= (unsigned)Hdim || (unsigned)ws >= (unsigned)Wdim)
            continue;
        int head = c >> 5;
        const float* wrow = s_w + (head * WS2 + i) * WS2;
        float acc = sb[head * WS2 + i];
        #pragma unroll
        for (int j = 0; j < WS2; j++)
            acc = fmaf(wrow[j], s_x[j * Cdim + c], acc);
        size_t o = ((size_t)b * (Hdim*Wdim) + hs * Wdim + ws) * Cdim + c;
        x2[o] = x[o] + acc;
    }
}

// ---------------- fp32 SGEMM, BM=128 BN=64 BK=16, 8x4 per thread -----------
// MODE 0: out = gelu(A@B + bias)        (fc1)
// MODE 1: out = res + (A@B + bias)      (fc2, residual add)
__device__ __forceinline__ float gelu_exact(float v) {
    return 0.5f * v * (1.0f + erff(v * 0.70710678118654752f));
}

template<int Kd, int Nd, int MODE>
__global__ void __launch_bounds__(256)
gemm_kernel(const float* __restrict__ A, const float* __restrict__ Bw,
            const float* __restrict__ bias, const float* __restrict__ res,
            float* __restrict__ out)
{
    constexpr int BM = 128, BN = 64, BK = 16;
    __shared__ float s_a[BK][BM];
    __shared__ float s_b[BK][BN];

    const int bm = blockIdx.y * BM;
    const int bn = blockIdx.x * BN;
    const int t  = threadIdx.x;
    const int ty = t >> 4, tx = t & 15;

    // loader mapping
    const int am = t >> 2;            // 0..63 (rows am, am+64)
    const int ak = (t & 3) * 4;       // 0,4,8,12
    const int bk = t >> 4;            // 0..15
    const int bq = (t & 15) * 4;      // 0..60

    float acc[8][4];
    #pragma unroll
    for (int i = 0; i < 8; i++)
        #pragma unroll
        for (int j = 0; j < 4; j++) acc[i][j] = 0.0f;

    for (int k0 = 0; k0 < Kd; k0 += BK) {
        float4 a0 = *(const float4*)(A + (size_t)(bm + am)      * Kd + k0 + ak);
        float4 a1 = *(const float4*)(A + (size_t)(bm + am + 64) * Kd + k0 + ak);
        float4 b0 = *(const float4*)(Bw + (size_t)(k0 + bk) * Nd + bn + bq);

        s_a[ak+0][am] = a0.x; s_a[ak+1][am] = a0.y;
        s_a[ak+2][am] = a0.z; s_a[ak+3][am] = a0.w;
        s_a[ak+0][am+64] = a1.x; s_a[ak+1][am+64] = a1.y;
        s_a[ak+2][am+64] = a1.z; s_a[ak+3][am+64] = a1.w;
        *(float4*)&s_b[bk][bq] = b0;
        __syncthreads();

        #pragma unroll
        for (int k = 0; k < BK; k++) {
            float4 ra0 = *(float4*)&s_a[k][ty * 8];
            float4 ra1 = *(float4*)&s_a[k][ty * 8 + 4];
            float4 rb  = *(float4*)&s_b[k][tx * 4];
            float ra[8] = {ra0.x, ra0.y, ra0.z, ra0.w, ra1.x, ra1.y, ra1.z, ra1.w};
            float rbv[4] = {rb.x, rb.y, rb.z, rb.w};
            #pragma unroll
            for (int i = 0; i < 8; i++)
                #pragma unroll
                for (int j = 0; j < 4; j++)
                    acc[i][j] = fmaf(ra[i], rbv[j], acc[i][j]);
        }
        __syncthreads();
    }

    float4 bb = *(const float4*)(bias + bn + tx * 4);
    #pragma unroll
    for (int i = 0; i < 8; i++) {
        int row = bm + ty * 8 + i;
        float4 o;
        o.x = acc[i][0] + bb.x;
        o.y = acc[i][1] + bb.y;
        o.z = acc[i][2] + bb.z;
        o.w = acc[i][3] + bb.w;
        if (MODE == 0) {
            o.x = gelu_exact(o.x); o.y = gelu_exact(o.y);
            o.z = gelu_exact(o.z); o.w = gelu_exact(o.w);
        } else {
            float4 r = *(const float4*)(res + (size_t)row * Nd + bn + tx * 4);
            o.x += r.x; o.y += r.y; o.z += r.z; o.w += r.w;
        }
        *(float4*)(out + (size_t)row * Nd + bn + tx * 4) = o;
    }
}

// ---------------- launch ----------------
extern "C" void kernel_launch(void* const* d_in, const int* in_sizes, int n_in,
                              void* d_out, int out_size)
{
    const float* x   = (const float*)d_in[0];
    const float* g1  = (const float*)d_in[1];
    const float* b1  = (const float*)d_in[2];
    const float* sw  = (const float*)d_in[3];
    const float* sb  = (const float*)d_in[4];
    const float* g2  = (const float*)d_in[5];
    const float* b2  = (const float*)d_in[6];
    const float* w1  = (const float*)d_in[7];
    const float* bb1 = (const float*)d_in[8];
    const float* w2  = (const float*)d_in[9];
    const float* bb2 = (const float*)d_in[10];
    float* out = (float*)d_out;

    float *xn, *x2, *hbuf;
    cudaGetSymbolAddress((void**)&xn,   g_xn);
    cudaGetSymbolAddress((void**)&x2,   g_x2);
    cudaGetSymbolAddress((void**)&hbuf, g_h);

    cudaFuncSetAttribute(spatial_kernel,
                         cudaFuncAttributeMaxDynamicSharedMemorySize,
                         (int)SPATIAL_SMEM);

    // 1) LN1
    ln_kernel<<<NTOK / 8, 256>>>(x, g1, b1, xn);
    // 2) shifted-window mixing + residual -> x2
    spatial_kernel<<<NWIN, 256, SPATIAL_SMEM>>>(xn, x, sw, sb, x2);
    // 3) LN2 (reuse xn buffer)
    ln_kernel<<<NTOK / 8, 256>>>(x2, g2, b2, xn);
    // 4) fc1 + GELU : (200704x128) @ (128x512)
    gemm_kernel<Cdim, HID, 0><<<dim3(HID / 64, NTOK / 128), 256>>>(xn, w1, bb1, nullptr, hbuf);
    // 5) fc2 + residual : (200704x512) @ (512x128) + x2
    gemm_kernel<HID, Cdim, 1><<<dim3(Cdim / 64, NTOK / 128), 256>>>(hbuf, w2, bb2, x2, out);
}

// round 2
// speedup vs baseline: 2.0250x; 2.0250x over previous
#include <cuda_runtime.h>
#include <math.h>
#include <stdint.h>

// ---------------- problem constants ----------------
#define BATCH 64
#define Hdim  56
#define Wdim  56
#define Cdim  128
#define HEADS 4
#define WSz   7
#define WS2   49
#define HID   512
#define NWG   9
#define NTOK  (BATCH*Hdim*Wdim)     // 200704
#define NWIN  (BATCH*NWG*NWG)       // 5184

// ---------------- scratch ----------------
__device__ float g_xn[(size_t)NTOK * Cdim];
__device__ float g_x2[(size_t)NTOK * Cdim];
__device__ float g_h [(size_t)NTOK * HID];

// =====================================================================
// Fused: LN1 -> shifted-window token mixing -> +residual -> LN2
// One block per 7x7 window (windows are disjoint and cover all tokens).
// Outputs: x2 (residual stream), xn2 (LN2 output = GEMM input).
// =====================================================================
#define WPAD 52   // padded weight row (49 -> 52 floats, 16B-aligned rows)
#define PRE_SMEM ((2*WS2*Cdim + HEADS*WS2*WPAD) * 4)   // 90944 B

__global__ void __launch_bounds__(256, 2) fused_pre(
    const float* __restrict__ x,
    const float* __restrict__ g1, const float* __restrict__ b1,
    const float* __restrict__ sw, const float* __restrict__ sb,
    const float* __restrict__ g2, const float* __restrict__ b2,
    float* __restrict__ x2, float* __restrict__ xn2)
{
    extern __shared__ float sm[];
    float* s_x = sm;                    // [49][128] raw x (later x2)
    float* s_n = sm + WS2 * Cdim;       // [49][128] LN1 output
    float* s_w = sm + 2 * WS2 * Cdim;   // [4*49][52] weights

    const int tid  = threadIdx.x;
    const int lane = tid & 31;
    const int warp = tid >> 5;

    const int win = blockIdx.x;
    const int b   = win / 81;
    const int wi  = win % 81;
    const int wh  = wi / 9, ww = wi % 9;

    const int c0 = lane * 4;             // channel group per lane
    const int headL = lane >> 3;         // head for this lane's channels

    const float4 g1v = *(const float4*)(g1 + c0);
    const float4 b1v = *(const float4*)(b1 + c0);
    const float4 g2v = *(const float4*)(g2 + c0);
    const float4 b2v = *(const float4*)(b2 + c0);

    // ---- load x tile (zero outside image: pad-after-LN semantics) ----
    for (int idx = tid; idx < WS2 * Cdim; idx += 256) {
        int j = idx >> 7, c = idx & 127;
        int hs = wh * 7 + j / 7 - 4;
        int ws = ww * 7 + j % 7 - 4;
        float v = 0.0f;
        if ((unsigned)hs < 56u && (unsigned)ws < 56u)
            v = x[((size_t)b * 3136 + hs * 56 + ws) * 128 + c];
        s_x[idx] = v;
    }
    // ---- load weights into padded rows ----
    for (int idx = tid; idx < HEADS * WS2 * WS2; idx += 256) {
        int row = idx / 49, j = idx % 49;
        s_w[row * WPAD + j] = sw[idx];
    }
    __syncthreads();

    // ---- LN1 per token (warp handles i = warp, warp+8, ...) ----
    #pragma unroll
    for (int ii = 0; ii < 7; ii++) {
        int i = warp + 8 * ii;
        if (i >= 49) continue;                      // warp-uniform
        int hs = wh * 7 + i / 7 - 4;
        int ws = ww * 7 + i % 7 - 4;
        bool valid = ((unsigned)hs < 56u) && ((unsigned)ws < 56u);  // warp-uniform
        float4 o4 = make_float4(0.f, 0.f, 0.f, 0.f);
        if (valid) {
            float4 v = *(float4*)(s_x + i * 128 + c0);
            float s  = v.x + v.y + v.z + v.w;
            float s2 = v.x*v.x + v.y*v.y + v.z*v.z + v.w*v.w;
            #pragma unroll
            for (int o = 16; o; o >>= 1) {
                s  += __shfl_xor_sync(0xffffffffu, s,  o);
                s2 += __shfl_xor_sync(0xffffffffu, s2, o);
            }
            float mu  = s * (1.0f / 128.0f);
            float inv = rsqrtf(s2 * (1.0f / 128.0f) - mu * mu + 1e-5f);
            o4.x = (v.x - mu) * inv * g1v.x + b1v.x;
            o4.y = (v.y - mu) * inv * g1v.y + b1v.y;
            o4.z = (v.z - mu) * inv * g1v.z + b1v.z;
            o4.w = (v.w - mu) * inv * g1v.w + b1v.w;
        }
        *(float4*)(s_n + i * 128 + c0) = o4;
    }
    __syncthreads();

    // ---- token mixing: y[i][c] = sum_j w[h,i,j]*xn[j][c] + sb[h,i] ----
    float4 acc[7];
    #pragma unroll
    for (int ii = 0; ii < 7; ii++) {
        int i = warp + 8 * ii;
        float bv = (i < 49) ? sb[headL * 49 + i] : 0.0f;
        acc[ii] = make_float4(bv, bv, bv, bv);
    }
    for (int j0 = 0; j0 < 48; j0 += 4) {
        float4 xv0 = *(float4*)(s_n + (j0 + 0) * 128 + c0);
        float4 xv1 = *(float4*)(s_n + (j0 + 1) * 128 + c0);
        float4 xv2 = *(float4*)(s_n + (j0 + 2) * 128 + c0);
        float4 xv3 = *(float4*)(s_n + (j0 + 3) * 128 + c0);
        #pragma unroll
        for (int ii = 0; ii < 7; ii++) {
            int i = warp + 8 * ii;
            if (i >= 49) continue;
            float4 wv = *(float4*)(s_w + (headL * 49 + i) * WPAD + j0);
            acc[ii].x += wv.x*xv0.x + wv.y*xv1.x + wv.z*xv2.x + wv.w*xv3.x;
            acc[ii].y += wv.x*xv0.y + wv.y*xv1.y + wv.z*xv2.y + wv.w*xv3.y;
            acc[ii].z += wv.x*xv0.z + wv.y*xv1.z + wv.z*xv2.z + wv.w*xv3.z;
            acc[ii].w += wv.x*xv0.w + wv.y*xv1.w + wv.z*xv2.w + wv.w*xv3.w;
        }
    }
    {   // remainder j = 48
        float4 xv = *(float4*)(s_n + 48 * 128 + c0);
        #pragma unroll
        for (int ii = 0; ii < 7; ii++) {
            int i = warp + 8 * ii;
            if (i >= 49) continue;
            float wv = s_w[(headL * 49 + i) * WPAD + 48];
            acc[ii].x += wv * xv.x; acc[ii].y += wv * xv.y;
            acc[ii].z += wv * xv.z; acc[ii].w += wv * xv.w;
        }
    }
    // residual: x2 = x + y (into s_x; each element touched only by its owner)
    #pragma unroll
    for (int ii = 0; ii < 7; ii++) {
        int i = warp + 8 * ii;
        if (i >= 49) continue;
        float4 xr = *(float4*)(s_x + i * 128 + c0);
        xr.x += acc[ii].x; xr.y += acc[ii].y;
        xr.z += acc[ii].z; xr.w += acc[ii].w;
        *(float4*)(s_x + i * 128 + c0) = xr;
    }
    __syncthreads();

    // ---- LN2 + global writes (valid tokens only) ----
    #pragma unroll
    for (int ii = 0; ii < 7; ii++) {
        int i = warp + 8 * ii;
        if (i >= 49) continue;
        int hs = wh * 7 + i / 7 - 4;
        int ws = ww * 7 + i % 7 - 4;
        if ((unsigned)hs >= 56u || (unsigned)ws >= 56u) continue;  // warp-uniform
        float4 v = *(float4*)(s_x + i * 128 + c0);
        float s  = v.x + v.y + v.z + v.w;
        float s2 = v.x*v.x + v.y*v.y + v.z*v.z + v.w*v.w;
        #pragma unroll
        for (int o = 16; o; o >>= 1) {
            s  += __shfl_xor_sync(0xffffffffu, s,  o);
            s2 += __shfl_xor_sync(0xffffffffu, s2, o);
        }
        float mu  = s * (1.0f / 128.0f);
        float inv = rsqrtf(s2 * (1.0f / 128.0f) - mu * mu + 1e-5f);
        size_t o = ((size_t)b * 3136 + hs * 56 + ws) * 128 + c0;
        *(float4*)(x2 + o) = v;
        float4 n4;
        n4.x = (v.x - mu) * inv * g2v.x + b2v.x;
        n4.y = (v.y - mu) * inv * g2v.y + b2v.y;
        n4.z = (v.z - mu) * inv * g2v.z + b2v.z;
        n4.w = (v.w - mu) * inv * g2v.w + b2v.w;
        *(float4*)(xn2 + o) = n4;
    }
}

// =====================================================================
// tf32 tensor-core GEMM: BM=128 BN=64 BK=32, 8 warps (4x2), warp=32x32.
// cp.async double-buffered. MODE 0: gelu(A@B+bias). MODE 1: res+(A@B+bias).
// =====================================================================
__device__ __forceinline__ uint32_t f2tf(float f) {
    uint32_t u;
    asm("cvt.rna.tf32.f32 %0, %1;" : "=r"(u) : "f"(f));
    return u;
}
__device__ __forceinline__ void cpasync16(uint32_t s, const void* g) {
    asm volatile("cp.async.cg.shared.global [%0], [%1], 16;\n" :: "r"(s), "l"(g));
}
__device__ __forceinline__ float gelu_exact(float v) {
    return 0.5f * v * (1.0f + erff(v * 0.70710678118654752f));
}

#define AST 36
#define BST 68
#define GEMM_SMEM ((2*128*AST + 2*32*BST) * 4)   // 54272 B

template<int Kd, int Nd, int MODE>
__global__ void __launch_bounds__(256)
gemm_tc(const float* __restrict__ A, const float* __restrict__ Bw,
        const float* __restrict__ bias, const float* __restrict__ res,
        float* __restrict__ out)
{
    constexpr int BM = 128, BN = 64, BK = 32;
    extern __shared__ float smem[];
    float* s_a = smem;                  // [2][128][AST]
    float* s_b = smem + 2 * BM * AST;   // [2][32][BST]

    const int tid  = threadIdx.x;
    const int lane = tid & 31;
    const int warp = tid >> 5;
    const int wm = warp >> 1, wn = warp & 1;
    const int bm = blockIdx.y * BM, bn = blockIdx.x * BN;
    const int t4 = lane >> 2, q = lane & 3;

    const uint32_t sa_s = (uint32_t)__cvta_generic_to_shared(s_a);
    const uint32_t sb_s = (uint32_t)__cvta_generic_to_shared(s_b);

    float acc[2][4][4];
    #pragma unroll
    for (int mi = 0; mi < 2; mi++)
        #pragma unroll
        for (int ni = 0; ni < 4; ni++)
            #pragma unroll
            for (int r = 0; r < 4; r++) acc[mi][ni][r] = 0.0f;

    auto loadAB = [&](int buf, int k0) {
        #pragma unroll
        for (int i = 0; i < 4; i++) {         // A: 1024 16B lines
            int l = tid + 256 * i;
            int r = l >> 3, cq = (l & 7) * 4;
            cpasync16(sa_s + (uint32_t)(((buf * BM + r) * AST + cq) * 4),
                      A + (size_t)(bm + r) * Kd + k0 + cq);
        }
        #pragma unroll
        for (int i = 0; i < 2; i++) {         // B: 512 16B lines
            int l = tid + 256 * i;
            int r = l >> 4, cq = (l & 15) * 4;
            cpasync16(sb_s + (uint32_t)(((buf * BK + r) * BST + cq) * 4),
                      Bw + (size_t)(k0 + r) * Nd + bn + cq);
        }
        asm volatile("cp.async.commit_group;\n");
    };

    constexpr int KT = Kd / BK;
    loadAB(0, 0);
    asm volatile("cp.async.wait_group 0;\n");
    __syncthreads();

    int buf = 0;
    for (int kt = 0; kt < KT; kt++) {
        if (kt + 1 < KT) loadAB(buf ^ 1, (kt + 1) * BK);

        const float* sa = s_a + buf * BM * AST;
        const float* sb = s_b + buf * BK * BST;
        #pragma unroll
        for (int ks = 0; ks < 4; ks++) {
            const int k = ks * 8;
            uint32_t a[2][4], bf[4][2];
            #pragma unroll
            for (int mi = 0; mi < 2; mi++) {
                int r = wm * 32 + mi * 16 + t4;
                a[mi][0] = f2tf(sa[(r    ) * AST + k + q    ]);
                a[mi][1] = f2tf(sa[(r + 8) * AST + k + q    ]);
                a[mi][2] = f2tf(sa[(r    ) * AST + k + q + 4]);
                a[mi][3] = f2tf(sa[(r + 8) * AST + k + q + 4]);
            }
            #pragma unroll
            for (int ni = 0; ni < 4; ni++) {
                int cc = wn * 32 + ni * 8 + t4;
                bf[ni][0] = f2tf(sb[(k + q    ) * BST + cc]);
                bf[ni][1] = f2tf(sb[(k + q + 4) * BST + cc]);
            }
            #pragma unroll
            for (int mi = 0; mi < 2; mi++)
                #pragma unroll
                for (int ni = 0; ni < 4; ni++)
                    asm volatile(
                        "mma.sync.aligned.m16n8k8.row.col.f32.tf32.tf32.f32 "
                        "{%0,%1,%2,%3},{%4,%5,%6,%7},{%8,%9},{%0,%1,%2,%3};\n"
                        : "+f"(acc[mi][ni][0]), "+f"(acc[mi][ni][1]),
                          "+f"(acc[mi][ni][2]), "+f"(acc[mi][ni][3])
                        : "r"(a[mi][0]), "r"(a[mi][1]), "r"(a[mi][2]), "r"(a[mi][3]),
                          "r"(bf[ni][0]), "r"(bf[ni][1]));
        }
        if (kt + 1 < KT) asm volatile("cp.async.wait_group 0;\n");
        __syncthreads();
        buf ^= 1;
    }

    // ---- epilogue ----
    #pragma unroll
    for (int mi = 0; mi < 2; mi++) {
        #pragma unroll
        for (int ni = 0; ni < 4; ni++) {
            int cc = bn + wn * 32 + ni * 8 + q * 2;
            int r0 = bm + wm * 32 + mi * 16 + t4;
            int r1 = r0 + 8;
            float bs0 = bias[cc], bs1 = bias[cc + 1];
            float2 v0 = make_float2(acc[mi][ni][0] + bs0, acc[mi][ni][1] + bs1);
            float2 v1 = make_float2(acc[mi][ni][2] + bs0, acc[mi][ni][3] + bs1);
            if (MODE == 0) {
                v0.x = gelu_exact(v0.x); v0.y = gelu_exact(v0.y);
                v1.x = gelu_exact(v1.x); v1.y = gelu_exact(v1.y);
            } else {
                float2 r0v = *(const float2*)(res + (size_t)r0 * Nd + cc);
                float2 r1v = *(const float2*)(res + (size_t)r1 * Nd + cc);
                v0.x += r0v.x; v0.y += r0v.y;
                v1.x += r1v.x; v1.y += r1v.y;
            }
            *(float2*)(out + (size_t)r0 * Nd + cc) = v0;
            *(float2*)(out + (size_t)r1 * Nd + cc) = v1;
        }
    }
}

// ---------------- launch ----------------
extern "C" void kernel_launch(void* const* d_in, const int* in_sizes, int n_in,
                              void* d_out, int out_size)
{
    const float* x   = (const float*)d_in[0];
    const float* g1  = (const float*)d_in[1];
    const float* b1  = (const float*)d_in[2];
    const float* sw  = (const float*)d_in[3];
    const float* sb  = (const float*)d_in[4];
    const float* g2  = (const float*)d_in[5];
    const float* b2  = (const float*)d_in[6];
    const float* w1  = (const float*)d_in[7];
    const float* bb1 = (const float*)d_in[8];
    const float* w2  = (const float*)d_in[9];
    const float* bb2 = (const float*)d_in[10];
    float* out = (float*)d_out;

    float *xn, *x2, *hbuf;
    cudaGetSymbolAddress((void**)&xn,   g_xn);
    cudaGetSymbolAddress((void**)&x2,   g_x2);
    cudaGetSymbolAddress((void**)&hbuf, g_h);

    cudaFuncSetAttribute(fused_pre,
                         cudaFuncAttributeMaxDynamicSharedMemorySize, PRE_SMEM);
    cudaFuncSetAttribute(gemm_tc<Cdim, HID, 0>,
                         cudaFuncAttributeMaxDynamicSharedMemorySize, GEMM_SMEM);
    cudaFuncSetAttribute(gemm_tc<HID, Cdim, 1>,
                         cudaFuncAttributeMaxDynamicSharedMemorySize, GEMM_SMEM);

    // 1) fused LN1 + window mixing + residual + LN2
    fused_pre<<<NWIN, 256, PRE_SMEM>>>(x, g1, b1, sw, sb, g2, b2, x2, xn);
    // 2) fc1 + GELU : (200704x128) @ (128x512)
    gemm_tc<Cdim, HID, 0><<<dim3(HID / 64, NTOK / 128), 256, GEMM_SMEM>>>(xn, w1, bb1, nullptr, hbuf);
    // 3) fc2 + residual : (200704x512) @ (512x128) + x2
    gemm_tc<HID, Cdim, 1><<<dim3(Cdim / 64, NTOK / 128), 256, GEMM_SMEM>>>(hbuf, w2, bb2, x2, out);
}